// round 2
// baseline (speedup 1.0000x reference)
#include <cuda_runtime.h>

#define NN 100000
#define NE 1600000
#define DIMH 128
#define DIMO 4

// ---------------- device scratch (no allocations allowed) ----------------
__device__ float g_h1[(size_t)NN * DIMH];   // x @ W1            (51.2 MB)
__device__ float g_h2[NN * DIMO];           // relu(agg+b1) @ W2 (1.6 MB)
__device__ int   g_deg[NN];
__device__ int   g_off[NN + 1];
__device__ int   g_cur[NN];
__device__ int   g_src[NE];                 // CSR src ids, grouped by dst
__device__ float g_dinv[NN];                // 1/sqrt(indeg+1)
__device__ int   g_is64;                    // edge_index dtype flag

// ---------------- dtype detection ----------------
// If edge_index is int64 (values < 2^31), every odd 32-bit word of the first
// 256 entries is 0. If int32, those words are random node ids (~never all 0).
__global__ void k_detect(const int* __restrict__ ei_raw) {
    int ok = 1;
    for (int i = 0; i < 256; i++)
        if (ei_raw[2 * i + 1] != 0) { ok = 0; break; }
    g_is64 = ok;
}

__device__ __forceinline__ int load_idx(const void* ei, long long pos) {
    if (g_is64) {
        long long v = ((const long long*)ei)[pos];
        return (int)v;
    } else {
        return ((const int*)ei)[pos];
    }
}

__device__ __forceinline__ int clampi(int v) {
    return v < 0 ? 0 : (v >= NN ? NN - 1 : v);
}

// ---------------- CSR build ----------------
__global__ void k_zero_deg() {
    int i = blockIdx.x * blockDim.x + threadIdx.x;
    if (i < NN) g_deg[i] = 0;
}

__global__ void k_hist(const void* __restrict__ ei) {
    int e = blockIdx.x * blockDim.x + threadIdx.x;
    if (e < NE) {
        int d = clampi(load_idx(ei, (long long)NE + e));
        atomicAdd(&g_deg[d], 1);
    }
}

// single-block exclusive scan over 100k degrees; also emits dinv and cursors
__global__ void k_scan() {
    __shared__ int sh[1024];
    __shared__ int carry;
    int tid = threadIdx.x;
    if (tid == 0) carry = 0;
    __syncthreads();
    for (int base = 0; base < NN; base += 1024) {
        int i = base + tid;
        int v = (i < NN) ? g_deg[i] : 0;
        sh[tid] = v;
        __syncthreads();
        for (int off = 1; off < 1024; off <<= 1) {
            int a = (tid >= off) ? sh[tid - off] : 0;
            __syncthreads();
            sh[tid] += a;
            __syncthreads();
        }
        int incl = sh[tid];
        int excl = carry + incl - v;
        if (i < NN) {
            g_off[i] = excl;
            g_cur[i] = excl;
            g_dinv[i] = rsqrtf((float)(v + 1));  // +1 self loop
        }
        __syncthreads();
        if (tid == 0) carry += sh[1023];
        __syncthreads();
    }
    if (tid == 0) g_off[NN] = carry;
}

__global__ void k_scatter(const void* __restrict__ ei) {
    int e = blockIdx.x * blockDim.x + threadIdx.x;
    if (e < NE) {
        int s = clampi(load_idx(ei, e));
        int d = clampi(load_idx(ei, (long long)NE + e));
        int p = atomicAdd(&g_cur[d], 1);
        if (p >= 0 && p < NE) g_src[p] = s;
    }
}

// ---------------- GEMM1: g_h1 = x @ W1  (100k x 128 @ 128 x 128) ----------------
// block = 256 threads, tile 64 rows x 128 cols, 8x4 micro-tile per thread
__global__ void k_gemm1(const float* __restrict__ x, const float* __restrict__ W) {
    __shared__ float xs[16][68];    // [k][row], transposed, padded
    __shared__ float ws[16][128];   // [k][col]
    int tid  = threadIdx.x;
    int row0 = blockIdx.x * 64;
    int tcol = (tid & 31) * 4;      // 0..124
    int trow = (tid >> 5) * 8;      // 0..56

    float acc[8][4];
#pragma unroll
    for (int r = 0; r < 8; r++)
#pragma unroll
        for (int c = 0; c < 4; c++) acc[r][c] = 0.f;

    for (int k0 = 0; k0 < 128; k0 += 16) {
        // load x tile: thread t -> row t/4, k-chunk (t%4)*4
        {
            int r  = tid >> 2;
            int kk = (tid & 3) * 4;
            int gr = row0 + r;
            float4 v = (gr < NN) ? *(const float4*)(x + (size_t)gr * 128 + k0 + kk)
                                 : make_float4(0.f, 0.f, 0.f, 0.f);
            xs[kk + 0][r] = v.x;
            xs[kk + 1][r] = v.y;
            xs[kk + 2][r] = v.z;
            xs[kk + 3][r] = v.w;
        }
        // load W tile: 16x128 = 512 float4, 2 per thread
#pragma unroll
        for (int i = tid; i < 512; i += 256) {
            int r = i >> 5;
            int c = (i & 31) * 4;
            *(float4*)&ws[r][c] = *(const float4*)(W + (size_t)(k0 + r) * 128 + c);
        }
        __syncthreads();
#pragma unroll
        for (int k = 0; k < 16; k++) {
            float4 wv = *(float4*)&ws[k][tcol];
            float xr[8];
            *(float4*)&xr[0] = *(float4*)&xs[k][trow];
            *(float4*)&xr[4] = *(float4*)&xs[k][trow + 4];
#pragma unroll
            for (int r = 0; r < 8; r++) {
                acc[r][0] += xr[r] * wv.x;
                acc[r][1] += xr[r] * wv.y;
                acc[r][2] += xr[r] * wv.z;
                acc[r][3] += xr[r] * wv.w;
            }
        }
        __syncthreads();
    }
#pragma unroll
    for (int r = 0; r < 8; r++) {
        int gr = row0 + trow + r;
        if (gr < NN) {
            float4 v = make_float4(acc[r][0], acc[r][1], acc[r][2], acc[r][3]);
            *(float4*)(g_h1 + (size_t)gr * 128 + tcol) = v;
        }
    }
}

// ---------------- Aggregation L1 (+ bias + relu) fused with GEMM2 ----------------
// one warp per node; lane covers 4 hidden dims via float4
__global__ void k_agg1(const float* __restrict__ b1, const float* __restrict__ W2) {
    int warp = (blockIdx.x * blockDim.x + threadIdx.x) >> 5;
    int lane = threadIdx.x & 31;
    if (warp >= NN) return;
    int i = warp;
    float di = g_dinv[i];

    float4 acc = *((const float4*)(g_h1 + (size_t)i * DIMH) + lane);
    float sw = di * di;                    // self-loop weight
    acc.x *= sw; acc.y *= sw; acc.z *= sw; acc.w *= sw;

    int beg = g_off[i], end = g_off[i + 1];
    for (int e0 = beg; e0 < end; e0 += 32) {
        int idx = e0 + lane;
        int s = 0; float w = 0.f;
        if (idx < end) { s = g_src[idx]; w = g_dinv[s]; }
        int m = min(32, end - e0);
        for (int j = 0; j < m; j++) {
            int   ss = __shfl_sync(0xffffffffu, s, j);
            float ww = __shfl_sync(0xffffffffu, w, j) * di;
            float4 v = *((const float4*)(g_h1 + (size_t)ss * DIMH) + lane);
            acc.x += v.x * ww; acc.y += v.y * ww;
            acc.z += v.z * ww; acc.w += v.w * ww;
        }
    }
    // bias + relu
    float4 bb = *((const float4*)b1 + lane);
    acc.x = fmaxf(acc.x + bb.x, 0.f);
    acc.y = fmaxf(acc.y + bb.y, 0.f);
    acc.z = fmaxf(acc.z + bb.z, 0.f);
    acc.w = fmaxf(acc.w + bb.w, 0.f);

    // fused GEMM2: h2[i] = relu_row @ W2   (W2 is [128][4], row = float4)
    float p0 = 0.f, p1 = 0.f, p2 = 0.f, p3 = 0.f;
    int kbase = lane * 4;
    {
        float xv; float4 wr;
        wr = *((const float4*)W2 + (kbase + 0)); xv = acc.x;
        p0 += xv * wr.x; p1 += xv * wr.y; p2 += xv * wr.z; p3 += xv * wr.w;
        wr = *((const float4*)W2 + (kbase + 1)); xv = acc.y;
        p0 += xv * wr.x; p1 += xv * wr.y; p2 += xv * wr.z; p3 += xv * wr.w;
        wr = *((const float4*)W2 + (kbase + 2)); xv = acc.z;
        p0 += xv * wr.x; p1 += xv * wr.y; p2 += xv * wr.z; p3 += xv * wr.w;
        wr = *((const float4*)W2 + (kbase + 3)); xv = acc.w;
        p0 += xv * wr.x; p1 += xv * wr.y; p2 += xv * wr.z; p3 += xv * wr.w;
    }
#pragma unroll
    for (int o = 16; o; o >>= 1) {
        p0 += __shfl_xor_sync(0xffffffffu, p0, o);
        p1 += __shfl_xor_sync(0xffffffffu, p1, o);
        p2 += __shfl_xor_sync(0xffffffffu, p2, o);
        p3 += __shfl_xor_sync(0xffffffffu, p3, o);
    }
    if (lane == 0)
        *((float4*)(g_h2 + (size_t)i * 4)) = make_float4(p0, p1, p2, p3);
}

// ---------------- Aggregation L2 (+ bias) -> out ----------------
__global__ void k_agg2(const float* __restrict__ b2, float* __restrict__ out) {
    int i = blockIdx.x * blockDim.x + threadIdx.x;
    if (i >= NN) return;
    float di = g_dinv[i];
    float4 h = *((const float4*)g_h2 + i);
    float sw = di * di;
    float4 acc = make_float4(h.x * sw, h.y * sw, h.z * sw, h.w * sw);
    int beg = g_off[i], end = g_off[i + 1];
    for (int e = beg; e < end; e++) {
        int s = g_src[e];
        float ww = g_dinv[s] * di;
        float4 v = *((const float4*)g_h2 + s);
        acc.x += v.x * ww; acc.y += v.y * ww;
        acc.z += v.z * ww; acc.w += v.w * ww;
    }
    float4 bb = *(const float4*)b2;
    acc.x += bb.x; acc.y += bb.y; acc.z += bb.z; acc.w += bb.w;
    *((float4*)out + i) = acc;
}

// ---------------- launch ----------------
extern "C" void kernel_launch(void* const* d_in, const int* in_sizes, int n_in,
                              void* d_out, int out_size) {
    const float* x  = (const float*)d_in[0];
    const void*  ei = d_in[1];
    const float* W1 = (const float*)d_in[2];
    const float* b1 = (const float*)d_in[3];
    const float* W2 = (const float*)d_in[4];
    const float* b2 = (const float*)d_in[5];
    float*       out = (float*)d_out;

    k_detect <<<1, 1>>>((const int*)ei);
    k_zero_deg<<<(NN + 255) / 256, 256>>>();
    k_hist   <<<(NE + 255) / 256, 256>>>(ei);
    k_scan   <<<1, 1024>>>();
    k_scatter<<<(NE + 255) / 256, 256>>>(ei);
    k_gemm1  <<<(NN + 63) / 64, 256>>>(x, W1);
    k_agg1   <<<(NN + 7) / 8, 256>>>(b1, W2);
    k_agg2   <<<(NN + 255) / 256, 256>>>(b2, out);
}

// round 5
// speedup vs baseline: 1.6306x; 1.6306x over previous
#include <cuda_runtime.h>

#define NN 100000
#define NE 1600000
#define DIMH 128
#define DIMO 4
#define NBLK ((NN + 1023) / 1024)   // 98 scan blocks

// ---------------- device scratch (no allocations allowed) ----------------
__device__ float g_h1[(size_t)NN * DIMH];   // x @ W1            (51.2 MB)
__device__ float g_h2[NN * DIMO];           // relu(agg+b1) @ W2 (1.6 MB)
__device__ int   g_deg[NN];
__device__ int   g_off[NN + 1];
__device__ int   g_cur[NN];
__device__ int   g_blk[NBLK];               // per-block totals / offsets
__device__ int   g_src[NE];                 // CSR src ids, grouped by dst
__device__ float g_dinv[NN];                // 1/sqrt(indeg+1)
__device__ int   g_is64;                    // edge_index dtype flag

// ---------------- dtype detection (1 warp, parallel loads) ----------------
// int64 edge_index with values < 2^31 => every odd 32-bit word of the first
// 256 entries is 0. int32 => those words are random node ids.
__global__ void k_detect(const int* __restrict__ ei_raw) {
    int lane = threadIdx.x;
    int ok = 1;
#pragma unroll
    for (int r = 0; r < 8; r++) {
        int idx = r * 32 + lane;             // entry idx, check odd word
        if (ei_raw[2 * idx + 1] != 0) ok = 0;
    }
    unsigned all = __all_sync(0xffffffffu, ok);
    if (lane == 0) g_is64 = all ? 1 : 0;
}

__device__ __forceinline__ int load_idx(const void* ei, long long pos) {
    if (g_is64) return (int)((const long long*)ei)[pos];
    return ((const int*)ei)[pos];
}

__device__ __forceinline__ int clampi(int v) {
    return v < 0 ? 0 : (v >= NN ? NN - 1 : v);
}

// ---------------- CSR build ----------------
__global__ void k_zero_deg() {
    int i = blockIdx.x * blockDim.x + threadIdx.x;
    if (i < NN) g_deg[i] = 0;
}

__global__ void k_hist(const void* __restrict__ ei) {
    int e = blockIdx.x * blockDim.x + threadIdx.x;
    if (e < NE) {
        int d = clampi(load_idx(ei, (long long)NE + e));
        atomicAdd(&g_deg[d], 1);
    }
}

// -------- scan pass 1: per-block exclusive scan (1024 elems/block) --------
__global__ void k_scan1() {
    __shared__ int wsum[32];
    int tid  = threadIdx.x;
    int lane = tid & 31, wid = tid >> 5;
    int i = blockIdx.x * 1024 + tid;
    int v = (i < NN) ? g_deg[i] : 0;

    // inclusive warp scan
    int s = v;
#pragma unroll
    for (int o = 1; o < 32; o <<= 1) {
        int t = __shfl_up_sync(0xffffffffu, s, o);
        if (lane >= o) s += t;
    }
    if (lane == 31) wsum[wid] = s;
    __syncthreads();
    if (wid == 0) {
        int ws = wsum[lane];
#pragma unroll
        for (int o = 1; o < 32; o <<= 1) {
            int t = __shfl_up_sync(0xffffffffu, ws, o);
            if (lane >= o) ws += t;
        }
        wsum[lane] = ws;
    }
    __syncthreads();
    int excl = s - v + (wid > 0 ? wsum[wid - 1] : 0);

    if (i < NN) {
        g_off[i]  = excl;                      // within-block offset for now
        g_dinv[i] = rsqrtf((float)(v + 1));    // +1 self loop
    }
    if (tid == 1023) g_blk[blockIdx.x] = excl + v;   // block total
}

// -------- scan pass 2: scan the 98 block totals (one small block) --------
__global__ void k_scan2() {
    int lane = threadIdx.x & 31, wid = threadIdx.x >> 5;  // 128 threads = 4 warps
    __shared__ int wsum[4];
    int v = (threadIdx.x < NBLK) ? g_blk[threadIdx.x] : 0;
    int s = v;
#pragma unroll
    for (int o = 1; o < 32; o <<= 1) {
        int t = __shfl_up_sync(0xffffffffu, s, o);
        if (lane >= o) s += t;
    }
    if (lane == 31) wsum[wid] = s;
    __syncthreads();
    int pre = 0;
    for (int w = 0; w < wid; w++) pre += wsum[w];
    int excl = pre + s - v;
    if (threadIdx.x < NBLK) g_blk[threadIdx.x] = excl;
    if (threadIdx.x == NBLK - 1) g_off[NN] = excl + v;   // total edge count
}

// -------- scan pass 3: add block offsets, emit cursors --------
__global__ void k_scan3() {
    int i = blockIdx.x * 1024 + threadIdx.x;
    if (i < NN) {
        int o = g_off[i] + g_blk[blockIdx.x];
        g_off[i] = o;
        g_cur[i] = o;
    }
}

__global__ void k_scatter(const void* __restrict__ ei) {
    int e = blockIdx.x * blockDim.x + threadIdx.x;
    if (e < NE) {
        int s = clampi(load_idx(ei, e));
        int d = clampi(load_idx(ei, (long long)NE + e));
        int p = atomicAdd(&g_cur[d], 1);
        if (p >= 0 && p < NE) g_src[p] = s;
    }
}

// ---------------- GEMM1: g_h1 = x @ W1  (100k x 128 @ 128 x 128) ----------------
__global__ void k_gemm1(const float* __restrict__ x, const float* __restrict__ W) {
    __shared__ float xs[16][68];    // [k][row], transposed, padded
    __shared__ float ws[16][128];   // [k][col]
    int tid  = threadIdx.x;
    int row0 = blockIdx.x * 64;
    int tcol = (tid & 31) * 4;      // 0..124
    int trow = (tid >> 5) * 8;      // 0..56

    float acc[8][4];
#pragma unroll
    for (int r = 0; r < 8; r++)
#pragma unroll
        for (int c = 0; c < 4; c++) acc[r][c] = 0.f;

    for (int k0 = 0; k0 < 128; k0 += 16) {
        {
            int r  = tid >> 2;
            int kk = (tid & 3) * 4;
            int gr = row0 + r;
            float4 v = (gr < NN) ? *(const float4*)(x + (size_t)gr * 128 + k0 + kk)
                                 : make_float4(0.f, 0.f, 0.f, 0.f);
            xs[kk + 0][r] = v.x;
            xs[kk + 1][r] = v.y;
            xs[kk + 2][r] = v.z;
            xs[kk + 3][r] = v.w;
        }
#pragma unroll
        for (int i = tid; i < 512; i += 256) {
            int r = i >> 5;
            int c = (i & 31) * 4;
            *(float4*)&ws[r][c] = *(const float4*)(W + (size_t)(k0 + r) * 128 + c);
        }
        __syncthreads();
#pragma unroll
        for (int k = 0; k < 16; k++) {
            float4 wv = *(float4*)&ws[k][tcol];
            float xr[8];
            *(float4*)&xr[0] = *(float4*)&xs[k][trow];
            *(float4*)&xr[4] = *(float4*)&xs[k][trow + 4];
#pragma unroll
            for (int r = 0; r < 8; r++) {
                acc[r][0] += xr[r] * wv.x;
                acc[r][1] += xr[r] * wv.y;
                acc[r][2] += xr[r] * wv.z;
                acc[r][3] += xr[r] * wv.w;
            }
        }
        __syncthreads();
    }
#pragma unroll
    for (int r = 0; r < 8; r++) {
        int gr = row0 + trow + r;
        if (gr < NN) {
            float4 v = make_float4(acc[r][0], acc[r][1], acc[r][2], acc[r][3]);
            *(float4*)(g_h1 + (size_t)gr * 128 + tcol) = v;
        }
    }
}

// ---------------- Aggregation L1 (+ bias + relu) fused with GEMM2 ----------------
__global__ void k_agg1(const float* __restrict__ b1, const float* __restrict__ W2) {
    int warp = (blockIdx.x * blockDim.x + threadIdx.x) >> 5;
    int lane = threadIdx.x & 31;
    if (warp >= NN) return;
    int i = warp;
    float di = g_dinv[i];

    float4 acc = *((const float4*)(g_h1 + (size_t)i * DIMH) + lane);
    float sw = di * di;                    // self-loop weight
    acc.x *= sw; acc.y *= sw; acc.z *= sw; acc.w *= sw;

    int beg = g_off[i], end = g_off[i + 1];
    for (int e0 = beg; e0 < end; e0 += 32) {
        int idx = e0 + lane;
        int s = 0; float w = 0.f;
        if (idx < end) { s = g_src[idx]; w = g_dinv[s]; }
        int m = min(32, end - e0);
        for (int j = 0; j < m; j++) {
            int   ss = __shfl_sync(0xffffffffu, s, j);
            float ww = __shfl_sync(0xffffffffu, w, j) * di;
            float4 v = *((const float4*)(g_h1 + (size_t)ss * DIMH) + lane);
            acc.x += v.x * ww; acc.y += v.y * ww;
            acc.z += v.z * ww; acc.w += v.w * ww;
        }
    }
    float4 bb = *((const float4*)b1 + lane);
    acc.x = fmaxf(acc.x + bb.x, 0.f);
    acc.y = fmaxf(acc.y + bb.y, 0.f);
    acc.z = fmaxf(acc.z + bb.z, 0.f);
    acc.w = fmaxf(acc.w + bb.w, 0.f);

    // fused GEMM2: h2[i] = relu_row @ W2   (W2 is [128][4])
    float p0 = 0.f, p1 = 0.f, p2 = 0.f, p3 = 0.f;
    int kbase = lane * 4;
    {
        float xv; float4 wr;
        wr = *((const float4*)W2 + (kbase + 0)); xv = acc.x;
        p0 += xv * wr.x; p1 += xv * wr.y; p2 += xv * wr.z; p3 += xv * wr.w;
        wr = *((const float4*)W2 + (kbase + 1)); xv = acc.y;
        p0 += xv * wr.x; p1 += xv * wr.y; p2 += xv * wr.z; p3 += xv * wr.w;
        wr = *((const float4*)W2 + (kbase + 2)); xv = acc.z;
        p0 += xv * wr.x; p1 += xv * wr.y; p2 += xv * wr.z; p3 += xv * wr.w;
        wr = *((const float4*)W2 + (kbase + 3)); xv = acc.w;
        p0 += xv * wr.x; p1 += xv * wr.y; p2 += xv * wr.z; p3 += xv * wr.w;
    }
#pragma unroll
    for (int o = 16; o; o >>= 1) {
        p0 += __shfl_xor_sync(0xffffffffu, p0, o);
        p1 += __shfl_xor_sync(0xffffffffu, p1, o);
        p2 += __shfl_xor_sync(0xffffffffu, p2, o);
        p3 += __shfl_xor_sync(0xffffffffu, p3, o);
    }
    if (lane == 0)
        *((float4*)(g_h2 + (size_t)i * 4)) = make_float4(p0, p1, p2, p3);
}

// ---------------- Aggregation L2 (+ bias) -> out ----------------
__global__ void k_agg2(const float* __restrict__ b2, float* __restrict__ out) {
    int i = blockIdx.x * blockDim.x + threadIdx.x;
    if (i >= NN) return;
    float di = g_dinv[i];
    float4 h = *((const float4*)g_h2 + i);
    float sw = di * di;
    float4 acc = make_float4(h.x * sw, h.y * sw, h.z * sw, h.w * sw);
    int beg = g_off[i], end = g_off[i + 1];
    for (int e = beg; e < end; e++) {
        int s = g_src[e];
        float ww = g_dinv[s] * di;
        float4 v = *((const float4*)g_h2 + s);
        acc.x += v.x * ww; acc.y += v.y * ww;
        acc.z += v.z * ww; acc.w += v.w * ww;
    }
    float4 bb = *(const float4*)b2;
    acc.x += bb.x; acc.y += bb.y; acc.z += bb.z; acc.w += bb.w;
    *((float4*)out + i) = acc;
}

// ---------------- launch ----------------
extern "C" void kernel_launch(void* const* d_in, const int* in_sizes, int n_in,
                              void* d_out, int out_size) {
    const float* x  = (const float*)d_in[0];
    const void*  ei = d_in[1];
    const float* W1 = (const float*)d_in[2];
    const float* b1 = (const float*)d_in[3];
    const float* W2 = (const float*)d_in[4];
    const float* b2 = (const float*)d_in[5];
    float*       out = (float*)d_out;

    k_detect  <<<1, 32>>>((const int*)ei);
    k_zero_deg<<<(NN + 255) / 256, 256>>>();
    k_hist    <<<(NE + 255) / 256, 256>>>(ei);
    k_scan1   <<<NBLK, 1024>>>();
    k_scan2   <<<1, 128>>>();
    k_scan3   <<<NBLK, 1024>>>();
    k_scatter <<<(NE + 255) / 256, 256>>>(ei);
    k_gemm1   <<<(NN + 63) / 64, 256>>>(x, W1);
    k_agg1    <<<(NN + 7) / 8, 256>>>(b1, W2);
    k_agg2    <<<(NN + 255) / 256, 256>>>(b2, out);
}